// round 6
// baseline (speedup 1.0000x reference)
#include <cuda_runtime.h>
#include <cstdint>
#include <math.h>

// ---------------- problem constants ----------------
#define FDIM 221
#define BATCH 2048
#define XS 224
#define NPAD 256
#define DDIM 13
#define SDIM 26
#define EDIM 8
#define VDIM 100000
#define TRI 24531             // F*(F+1)/2 valid triangle rows
#define TRIP2 24576           // padded K, multiple of 64
#define BKC 64
#define CHUNKS (TRIP2 / BKC)  // 384
#define KSPLIT 9
#define CPS 43                // ceil(384/9); last split gets 40
#define BM 64

// ---------------- gemm smem layout (dynamic) ----------------
#define W_STG (BKC * NPAD * 4)          // 65536 B
#define A_STG (BKC * BM * 8)            // 32768 B (f32x2 duplicated pairs)
#define OFF_W0 0
#define OFF_W1 W_STG
#define OFF_A0 (2 * W_STG)
#define OFF_A1 (2 * W_STG + A_STG)
#define SMEM_GEMM (2 * W_STG + 2 * A_STG)   // 196608 B

// ---------------- scratch (device globals; no allocation APIs) ----------------
__device__ float d_X1[BATCH * XS];
__device__ float d_X2[BATCH * XS];
__device__ float d_Wp1[(size_t)TRIP2 * NPAD];          // 25.2 MB folded W1
__device__ float d_Yp[(size_t)KSPLIT * BATCH * NPAD];  // 18.9 MB split-K partials
__device__ float d_w2t[TRIP2];                         // folded column-sums of W2
__device__ float d_b2s;
__device__ __align__(16) int d_Tij[TRIP2];             // i | (j<<16)

// ---------------- helpers ----------------
__device__ __forceinline__ uint32_t smem_u32(const void* p) {
    uint32_t a;
    asm("{ .reg .u64 t; cvta.to.shared.u64 t, %1; cvt.u32.u64 %0, t; }" : "=r"(a) : "l"(p));
    return a;
}
__device__ __forceinline__ void cpa16(uint32_t sm, const void* g) {
    asm volatile("cp.async.cg.shared.global [%0], [%1], 16;" :: "r"(sm), "l"(g));
}
__device__ __forceinline__ void fma2(unsigned long long& acc,
                                     unsigned long long a,
                                     unsigned long long b) {
    asm("fma.rn.f32x2 %0, %1, %2, %0;" : "+l"(acc) : "l"(a), "l"(b));
}
__device__ __forceinline__ float2 unpack2f(unsigned long long v) {
    float2 f;
    asm("mov.b64 {%0, %1}, %2;" : "=f"(f.x), "=f"(f.y) : "l"(v));
    return f;
}

// ---------------- 1) packed triangle index table ----------------
__global__ void make_pairs_kernel() {
    int tid = threadIdx.x;
    for (int i = tid; i < FDIM; i += blockDim.x) {
        int start = i * FDIM - (i * (i - 1)) / 2;
        for (int j = i; j < FDIM; j++)
            d_Tij[start + j - i] = i | (j << 16);
    }
    for (int r = TRI + tid; r < TRIP2; r += blockDim.x) d_Tij[r] = 0;
}

// ---------------- 2) fold W1 -> Wp1[TRIP2][256] ----------------
__global__ void pack1_kernel(const float* __restrict__ W) {
    int r = blockIdx.x;
    float* dst = d_Wp1 + (size_t)r * NPAD;
    if (r >= TRI) {
        for (int c = threadIdx.x; c < NPAD; c += blockDim.x) dst[c] = 0.f;
        return;
    }
    int p = d_Tij[r];
    int i = p & 0xffff, j = p >> 16;
    const float* wa = W + ((size_t)i * FDIM + j) * FDIM;
    const float* wb = W + ((size_t)j * FDIM + i) * FDIM;
    for (int c = threadIdx.x; c < NPAD; c += blockDim.x) {
        float v = 0.f;
        if (c < FDIM) {
            v = wa[c];
            if (i != j) v += wb[c];
        }
        dst[c] = v;
    }
}

// ---------------- 3) fold column-sums of W2 -> w2t (layer 2 collapses to a quadratic form) ----------------
__global__ void w2sum_kernel(const float* __restrict__ W2) {
    int r = blockIdx.x * 8 + (threadIdx.x >> 5);
    int lane = threadIdx.x & 31;
    if (r >= TRIP2) return;
    float s = 0.f;
    if (r < TRI) {
        int p = d_Tij[r];
        int i = p & 0xffff, j = p >> 16;
        const float* wa = W2 + ((size_t)i * FDIM + j) * FDIM;
        const float* wb = W2 + ((size_t)j * FDIM + i) * FDIM;
        for (int f = lane; f < FDIM; f += 32) {
            s += wa[f];
            if (i != j) s += wb[f];
        }
    }
#pragma unroll
    for (int o = 16; o > 0; o >>= 1) s += __shfl_down_sync(0xffffffffu, s, o);
    if (lane == 0) d_w2t[r] = s;
}
__global__ void b2sum_kernel(const float* __restrict__ b2) {
    __shared__ float red[8];
    int lane = threadIdx.x & 31, warp = threadIdx.x >> 5;
    float s = 0.f;
    for (int f = threadIdx.x; f < FDIM; f += 256) s += b2[f];
#pragma unroll
    for (int o = 16; o > 0; o >>= 1) s += __shfl_down_sync(0xffffffffu, s, o);
    if (lane == 0) red[warp] = s;
    __syncthreads();
    if (threadIdx.x == 0) {
        float t = 0.f;
#pragma unroll
        for (int w = 0; w < 8; w++) t += red[w];
        d_b2s = t;
    }
}

// ---------------- 4) build x = [dense | emb] ----------------
__global__ void build_x_kernel(const float* __restrict__ dense,
                               const int* __restrict__ sparse,
                               const float* __restrict__ emb) {
    int b = blockIdx.x;
    int t = threadIdx.x;
    float v = 0.f;
    if (t < DDIM) {
        v = dense[b * DDIM + t];
    } else if (t < FDIM) {
        int q = t - DDIM;
        int s = q >> 3;
        int e = q & 7;
        int idx = sparse[b * SDIM + s];
        v = emb[((size_t)s * VDIM + idx) * EDIM + e];
    }
    d_X1[b * XS + t] = v;
}

// ---------------- 5) layer-1 interaction GEMM (FFMA2, BK=64, split-K=9, 1 CTA/SM) ----------------
__global__ void __launch_bounds__(256) gemm1_kernel() {
    extern __shared__ __align__(16) char smem[];
    const uint32_t sb = smem_u32(smem);
    float* Wsm0 = (float*)(smem + OFF_W0);
    float* Wsm1 = (float*)(smem + OFF_W1);
    float2* Asm0 = (float2*)(smem + OFF_A0);
    float2* Asm1 = (float2*)(smem + OFF_A1);

    const int tid = threadIdx.x;
    const int colg = tid & 31;     // n pairs: colg*2 + s*64
    const int rowg = tid >> 5;     // m: rowg*8 .. +7
    const int mBase = blockIdx.x * BM;
    const int split = blockIdx.y;
    const int c0 = split * CPS;
    const int c1 = min(c0 + CPS, CHUNKS);
    const int am = tid & 63;       // A-build: fixed m per thread
    const int akg = tid >> 6;      // kk group 0..3 (16 kks each)
    const float* xr = d_X1 + (size_t)(mBase + am) * XS;

    unsigned long long acc[8][4];
#pragma unroll
    for (int a = 0; a < 8; a++)
#pragma unroll
        for (int s = 0; s < 4; s++) acc[a][s] = 0ULL;

    auto issueW = [&](int ch, int stg) {
        const char* g = (const char*)d_Wp1 + (size_t)ch * W_STG;
        const uint32_t s0 = sb + (stg ? OFF_W1 : OFF_W0);
#pragma unroll
        for (int q = 0; q < 16; q++) {
            const int off = (tid + q * 256) * 16;
            cpa16(s0 + off, g + off);
        }
        asm volatile("cp.async.commit_group;");
    };

    int tij[16];
    float xv[32];
    auto loadNext = [&](int ch) {
        const int rb = ch * BKC + akg * 16;
        const int4* t4 = (const int4*)(d_Tij + rb);
#pragma unroll
        for (int q = 0; q < 4; q++) {
            int4 p = __ldg(t4 + q);
            tij[q * 4 + 0] = p.x; tij[q * 4 + 1] = p.y;
            tij[q * 4 + 2] = p.z; tij[q * 4 + 3] = p.w;
        }
#pragma unroll
        for (int u = 0; u < 16; u++) {
            xv[2 * u]     = __ldg(xr + (tij[u] & 0xffff));
            xv[2 * u + 1] = __ldg(xr + (tij[u] >> 16));
        }
    };
    auto storeA = [&](int stg) {
        float2* dst = stg ? Asm1 : Asm0;
#pragma unroll
        for (int u = 0; u < 16; u++) {
            const float v = xv[2 * u] * xv[2 * u + 1];
            dst[(akg * 16 + u) * BM + am] = make_float2(v, v);
        }
    };

    // prologue
    issueW(c0, 0);
    loadNext(c0);
    storeA(0);
    asm volatile("cp.async.wait_group 0;");
    __syncthreads();

    for (int ch = c0; ch < c1; ch++) {
        const int buf = (ch - c0) & 1;
        const bool hasNext = (ch + 1 < c1);
        if (hasNext) {
            issueW(ch + 1, buf ^ 1);
            loadNext(ch + 1);      // LDGs in flight under the MMA block
        }
        const float* Wb = buf ? Wsm1 : Wsm0;
        const float2* Ab = buf ? Asm1 : Asm0;
#pragma unroll 8
        for (int kk = 0; kk < BKC; kk++) {
            const float2* ar = Ab + kk * BM + rowg * 8;
            ulonglong2 a01 = *reinterpret_cast<const ulonglong2*>(ar);
            ulonglong2 a23 = *reinterpret_cast<const ulonglong2*>(ar + 2);
            ulonglong2 a45 = *reinterpret_cast<const ulonglong2*>(ar + 4);
            ulonglong2 a67 = *reinterpret_cast<const ulonglong2*>(ar + 6);
            unsigned long long ap[8] = {a01.x, a01.y, a23.x, a23.y,
                                        a45.x, a45.y, a67.x, a67.y};
            unsigned long long wv[4];
            const float* wr = Wb + kk * NPAD + colg * 2;
#pragma unroll
            for (int s = 0; s < 4; s++)
                wv[s] = *reinterpret_cast<const unsigned long long*>(wr + s * 64);
#pragma unroll
            for (int tm = 0; tm < 8; tm++)
#pragma unroll
                for (int s = 0; s < 4; s++)
                    fma2(acc[tm][s], ap[tm], wv[s]);
        }
        if (hasNext) storeA(buf ^ 1);   // quick: products + 16 STS.64
        asm volatile("cp.async.wait_group 0;");
        __syncthreads();
    }

    // deterministic split-K partial store (coalesced float2)
#pragma unroll
    for (int tm = 0; tm < 8; tm++) {
        const int row = mBase + rowg * 8 + tm;
        float* dst = d_Yp + ((size_t)split * BATCH + row) * NPAD;
#pragma unroll
        for (int s = 0; s < 4; s++) {
            const int col = colg * 2 + s * 64;
            *reinterpret_cast<float2*>(dst + col) = unpack2f(acc[tm][s]);
        }
    }
}

// ---------------- 6) reduce split-K partials + bias -> X2 (zero-padded to 224) ----------------
__global__ void reduce1_kernel(const float* __restrict__ b1) {
    int m = blockIdx.x;
    int c = threadIdx.x;
    float v = 0.f;
    if (c < FDIM) {
        v = b1[c];
#pragma unroll
        for (int p = 0; p < KSPLIT; p++)
            v += d_Yp[((size_t)p * BATCH + m) * NPAD + c];
    }
    d_X2[m * XS + c] = v;
}

// ---------------- 7) final: pooled = x2^T S2 x2 + sum(b2); sigmoid ----------------
#define RPB 4
__global__ void final_kernel(const float* __restrict__ out_w,
                             const float* __restrict__ out_b,
                             float* __restrict__ out) {
    __shared__ float xs[RPB][XS];
    __shared__ float red[8][RPB];
    const int tid = threadIdx.x;
    const int b0 = blockIdx.x * RPB;
    for (int idx = tid; idx < RPB * XS; idx += 256)
        xs[idx / XS][idx % XS] = d_X2[(size_t)(b0 + idx / XS) * XS + (idx % XS)];
    __syncthreads();

    float acc[RPB] = {0.f, 0.f, 0.f, 0.f};
    for (int r = tid; r < TRIP2; r += 256) {
        const float w = __ldg(&d_w2t[r]);
        const int p = __ldg(&d_Tij[r]);
        const int i = p & 0xffff, j = p >> 16;
#pragma unroll
        for (int q = 0; q < RPB; q++)
            acc[q] += xs[q][i] * xs[q][j] * w;
    }
    const int lane = tid & 31, warp = tid >> 5;
#pragma unroll
    for (int q = 0; q < RPB; q++) {
        float s = acc[q];
#pragma unroll
        for (int o = 16; o > 0; o >>= 1) s += __shfl_down_sync(0xffffffffu, s, o);
        if (lane == 0) red[warp][q] = s;
    }
    __syncthreads();
    if (tid < RPB) {
        float s = 0.f;
#pragma unroll
        for (int w = 0; w < 8; w++) s += red[w][tid];
        const float pooled = s + d_b2s;
        const float z = pooled * out_w[0] + out_b[0];
        out[b0 + tid] = 1.f / (1.f + expf(-z));
    }
}

extern "C" void kernel_launch(void* const* d_in, const int* in_sizes, int n_in,
                              void* d_out, int out_size) {
    const float* dense = (const float*)d_in[0];
    const int* sparse = (const int*)d_in[1];
    const float* emb = (const float*)d_in[2];
    const float* W1 = (const float*)d_in[3];
    const float* b1 = (const float*)d_in[4];
    const float* W2 = (const float*)d_in[5];
    const float* b2 = (const float*)d_in[6];
    // d_in[7..10]: attention weights — mathematically dead (softmax over size-1 axis == 1)
    const float* out_w = (const float*)d_in[11];
    const float* out_b = (const float*)d_in[12];
    float* out = (float*)d_out;

    cudaFuncSetAttribute(gemm1_kernel, cudaFuncAttributeMaxDynamicSharedMemorySize, SMEM_GEMM);

    make_pairs_kernel<<<1, 256>>>();
    pack1_kernel<<<TRIP2, 64>>>(W1);
    w2sum_kernel<<<(TRIP2 + 7) / 8, 256>>>(W2);
    b2sum_kernel<<<1, 256>>>(b2);
    build_x_kernel<<<BATCH, XS>>>(dense, sparse, emb);

    gemm1_kernel<<<dim3(BATCH / BM, KSPLIT), 256, SMEM_GEMM>>>();
    reduce1_kernel<<<BATCH, XS>>>(b1);
    final_kernel<<<BATCH / RPB, 256>>>(out_w, out_b, out);
}

// round 7
// speedup vs baseline: 1.0302x; 1.0302x over previous
#include <cuda_runtime.h>
#include <cstdint>
#include <math.h>

// ---------------- problem constants ----------------
#define FDIM 221
#define BATCH 2048
#define XS 224
#define NPAD 256
#define DDIM 13
#define SDIM 26
#define EDIM 8
#define VDIM 100000
#define TRI 24531             // F*(F+1)/2 valid triangle rows
#define TRIP2 24544           // padded K, multiple of 32
#define BKC 32
#define CHUNKS (TRIP2 / BKC)  // 767
#define KSPLIT 9
#define CPS 86                // ceil(767/9)
#define BM 64

// ---------------- gemm smem layout (dynamic) ----------------
#define W_STG (BKC * NPAD * 4)          // 32768 B
#define A_STG (BKC * BM * 8)            // 16384 B (f32x2 duplicated pairs)
#define OFF_W0 0
#define OFF_W1 W_STG
#define OFF_A0 (2 * W_STG)
#define OFF_A1 (2 * W_STG + A_STG)
#define SMEM_GEMM (2 * W_STG + 2 * A_STG)   // 98304 B

// ---------------- scratch (device globals; no allocation APIs) ----------------
__device__ float d_X1[BATCH * XS];
__device__ float d_X2[BATCH * XS];
__device__ float d_Wp1[(size_t)TRIP2 * NPAD];          // 25.1 MB folded W1
__device__ float d_Yp[(size_t)KSPLIT * BATCH * NPAD];  // 18.9 MB split-K partials
__device__ float d_w2t[TRIP2];                         // folded column-sums of W2
__device__ float d_b2s;
__device__ __align__(16) int d_Tij[TRIP2];             // i | (j<<16)

// ---------------- helpers ----------------
__device__ __forceinline__ uint32_t smem_u32(const void* p) {
    uint32_t a;
    asm("{ .reg .u64 t; cvta.to.shared.u64 t, %1; cvt.u32.u64 %0, t; }" : "=r"(a) : "l"(p));
    return a;
}
__device__ __forceinline__ void cpa16(uint32_t sm, const void* g) {
    asm volatile("cp.async.cg.shared.global [%0], [%1], 16;" :: "r"(sm), "l"(g));
}
__device__ __forceinline__ void fma2(unsigned long long& acc,
                                     unsigned long long a,
                                     unsigned long long b) {
    asm("fma.rn.f32x2 %0, %1, %2, %0;" : "+l"(acc) : "l"(a), "l"(b));
}
__device__ __forceinline__ float2 unpack2f(unsigned long long v) {
    float2 f;
    asm("mov.b64 {%0, %1}, %2;" : "=f"(f.x), "=f"(f.y) : "l"(v));
    return f;
}

// ---------------- 1) packed triangle index table ----------------
__global__ void make_pairs_kernel() {
    int tid = threadIdx.x;
    for (int i = tid; i < FDIM; i += blockDim.x) {
        int start = i * FDIM - (i * (i - 1)) / 2;
        for (int j = i; j < FDIM; j++)
            d_Tij[start + j - i] = i | (j << 16);
    }
    for (int r = TRI + tid; r < TRIP2; r += blockDim.x) d_Tij[r] = 0;
}

// ---------------- 2) fold W1 -> Wp1[TRIP2][256] ----------------
__global__ void pack1_kernel(const float* __restrict__ W) {
    int r = blockIdx.x;
    float* dst = d_Wp1 + (size_t)r * NPAD;
    if (r >= TRI) {
        for (int c = threadIdx.x; c < NPAD; c += blockDim.x) dst[c] = 0.f;
        return;
    }
    int p = d_Tij[r];
    int i = p & 0xffff, j = p >> 16;
    const float* wa = W + ((size_t)i * FDIM + j) * FDIM;
    const float* wb = W + ((size_t)j * FDIM + i) * FDIM;
    for (int c = threadIdx.x; c < NPAD; c += blockDim.x) {
        float v = 0.f;
        if (c < FDIM) {
            v = wa[c];
            if (i != j) v += wb[c];
        }
        dst[c] = v;
    }
}

// ---------------- 3) fold column-sums of W2 -> w2t (layer 2 collapses to a quadratic form) ----------------
__global__ void w2sum_kernel(const float* __restrict__ W2) {
    int r = blockIdx.x * 8 + (threadIdx.x >> 5);
    int lane = threadIdx.x & 31;
    if (r >= TRIP2) return;
    float s = 0.f;
    if (r < TRI) {
        int p = d_Tij[r];
        int i = p & 0xffff, j = p >> 16;
        const float* wa = W2 + ((size_t)i * FDIM + j) * FDIM;
        const float* wb = W2 + ((size_t)j * FDIM + i) * FDIM;
        for (int f = lane; f < FDIM; f += 32) {
            s += wa[f];
            if (i != j) s += wb[f];
        }
    }
#pragma unroll
    for (int o = 16; o > 0; o >>= 1) s += __shfl_down_sync(0xffffffffu, s, o);
    if (lane == 0) d_w2t[r] = s;
}
__global__ void b2sum_kernel(const float* __restrict__ b2) {
    __shared__ float red[8];
    int lane = threadIdx.x & 31, warp = threadIdx.x >> 5;
    float s = 0.f;
    for (int f = threadIdx.x; f < FDIM; f += 256) s += b2[f];
#pragma unroll
    for (int o = 16; o > 0; o >>= 1) s += __shfl_down_sync(0xffffffffu, s, o);
    if (lane == 0) red[warp] = s;
    __syncthreads();
    if (threadIdx.x == 0) {
        float t = 0.f;
#pragma unroll
        for (int w = 0; w < 8; w++) t += red[w];
        d_b2s = t;
    }
}

// ---------------- 4) build x = [dense | emb] ----------------
__global__ void build_x_kernel(const float* __restrict__ dense,
                               const int* __restrict__ sparse,
                               const float* __restrict__ emb) {
    int b = blockIdx.x;
    int t = threadIdx.x;
    float v = 0.f;
    if (t < DDIM) {
        v = dense[b * DDIM + t];
    } else if (t < FDIM) {
        int q = t - DDIM;
        int s = q >> 3;
        int e = q & 7;
        int idx = sparse[b * SDIM + s];
        v = emb[((size_t)s * VDIM + idx) * EDIM + e];
    }
    d_X1[b * XS + t] = v;
}

// ---------------- 5) layer-1 interaction GEMM (FFMA2, BK=32, split-K=9, 2 CTA/SM) ----------------
__global__ void __launch_bounds__(256, 2) gemm1_kernel() {
    extern __shared__ __align__(16) char smem[];
    float* Wsm0 = (float*)(smem + OFF_W0);
    float* Wsm1 = (float*)(smem + OFF_W1);
    float2* Asm0 = (float2*)(smem + OFF_A0);
    float2* Asm1 = (float2*)(smem + OFF_A1);
    const uint32_t sb = smem_u32(smem);

    const int tid = threadIdx.x;
    const int colg = tid & 31;     // this thread owns cols colg*8 .. colg*8+7
    const int rowg = tid >> 5;     // m: rowg*8 .. +7
    const int mBase = blockIdx.x * BM;
    const int split = blockIdx.y;
    const int c0 = split * CPS;
    const int c1 = min(c0 + CPS, CHUNKS);
    const int am = tid & 63;       // A-build: fixed m per thread
    const int akg = tid >> 6;      // kk group 0..3 (8 kks each)
    const float* xr = d_X1 + (size_t)(mBase + am) * XS;

    unsigned long long acc[8][4];  // [m][pair s]: cols colg*8 + 2s, +1
#pragma unroll
    for (int a = 0; a < 8; a++)
#pragma unroll
        for (int s = 0; s < 4; s++) acc[a][s] = 0ULL;

    auto issueW = [&](int ch, int stg) {
        const char* g = (const char*)d_Wp1 + (size_t)ch * W_STG;
        const uint32_t s0 = sb + (stg ? OFF_W1 : OFF_W0);
#pragma unroll
        for (int q = 0; q < 8; q++) {
            const int off = (tid + q * 256) * 16;
            cpa16(s0 + off, g + off);
        }
        asm volatile("cp.async.commit_group;");
    };

    int tij[8];
    float xv[16];
    auto loadNext = [&](int ch) {
        const int rb = ch * BKC + akg * 8;
        const int4* t4 = (const int4*)(d_Tij + rb);
        int4 p0 = __ldg(t4);
        int4 p1 = __ldg(t4 + 1);
        tij[0] = p0.x; tij[1] = p0.y; tij[2] = p0.z; tij[3] = p0.w;
        tij[4] = p1.x; tij[5] = p1.y; tij[6] = p1.z; tij[7] = p1.w;
#pragma unroll
        for (int u = 0; u < 8; u++) {
            xv[2 * u]     = __ldg(xr + (tij[u] & 0xffff));
            xv[2 * u + 1] = __ldg(xr + (tij[u] >> 16));
        }
    };
    auto storeA = [&](int stg) {
        float2* dst = stg ? Asm1 : Asm0;
#pragma unroll
        for (int u = 0; u < 8; u++) {
            const float v = xv[2 * u] * xv[2 * u + 1];
            dst[(akg * 8 + u) * BM + am] = make_float2(v, v);
        }
    };

    // prologue
    issueW(c0, 0);
    loadNext(c0);
    storeA(0);
    asm volatile("cp.async.wait_group 0;");
    __syncthreads();

    for (int ch = c0; ch < c1; ch++) {
        const int buf = (ch - c0) & 1;
        const bool hasNext = (ch + 1 < c1);
        if (hasNext) {
            issueW(ch + 1, buf ^ 1);
            loadNext(ch + 1);      // LDGs in flight under the MMA block
        }
        const float* Wb = buf ? Wsm1 : Wsm0;
        const float2* Ab = buf ? Asm1 : Asm0;
#pragma unroll 8
        for (int kk = 0; kk < BKC; kk++) {
            const float2* ar = Ab + kk * BM + rowg * 8;
            ulonglong2 a01 = *reinterpret_cast<const ulonglong2*>(ar);
            ulonglong2 a23 = *reinterpret_cast<const ulonglong2*>(ar + 2);
            ulonglong2 a45 = *reinterpret_cast<const ulonglong2*>(ar + 4);
            ulonglong2 a67 = *reinterpret_cast<const ulonglong2*>(ar + 6);
            unsigned long long ap[8] = {a01.x, a01.y, a23.x, a23.y,
                                        a45.x, a45.y, a67.x, a67.y};
            // W: 8 consecutive cols per thread -> 2 x LDS.128
            const float* wr = Wb + kk * NPAD + colg * 8;
            ulonglong2 w01 = *reinterpret_cast<const ulonglong2*>(wr);
            ulonglong2 w23 = *reinterpret_cast<const ulonglong2*>(wr + 4);
            unsigned long long wv[4] = {w01.x, w01.y, w23.x, w23.y};
#pragma unroll
            for (int tm = 0; tm < 8; tm++)
#pragma unroll
                for (int s = 0; s < 4; s++)
                    fma2(acc[tm][s], ap[tm], wv[s]);
        }
        if (hasNext) storeA(buf ^ 1);   // quick: products + 8 STS.64
        asm volatile("cp.async.wait_group 0;");
        __syncthreads();
    }

    // deterministic split-K partial store (2 x STG.128 per row, coalesced)
#pragma unroll
    for (int tm = 0; tm < 8; tm++) {
        const int row = mBase + rowg * 8 + tm;
        float* dst = d_Yp + ((size_t)split * BATCH + row) * NPAD + colg * 8;
        float2 p0 = unpack2f(acc[tm][0]);
        float2 p1 = unpack2f(acc[tm][1]);
        float2 p2 = unpack2f(acc[tm][2]);
        float2 p3 = unpack2f(acc[tm][3]);
        *reinterpret_cast<float4*>(dst)     = make_float4(p0.x, p0.y, p1.x, p1.y);
        *reinterpret_cast<float4*>(dst + 4) = make_float4(p2.x, p2.y, p3.x, p3.y);
    }
}

// ---------------- 6) reduce split-K partials + bias -> X2 (zero-padded to 224) ----------------
__global__ void reduce1_kernel(const float* __restrict__ b1) {
    int m = blockIdx.x;
    int c = threadIdx.x;
    float v = 0.f;
    if (c < FDIM) {
        v = b1[c];
#pragma unroll
        for (int p = 0; p < KSPLIT; p++)
            v += d_Yp[((size_t)p * BATCH + m) * NPAD + c];
    }
    d_X2[m * XS + c] = v;
}

// ---------------- 7) final: pooled = x2^T S2 x2 + sum(b2); sigmoid ----------------
#define RPB 4
__global__ void final_kernel(const float* __restrict__ out_w,
                             const float* __restrict__ out_b,
                             float* __restrict__ out) {
    __shared__ float xs[RPB][XS];
    __shared__ float red[8][RPB];
    const int tid = threadIdx.x;
    const int b0 = blockIdx.x * RPB;
    for (int idx = tid; idx < RPB * XS; idx += 256)
        xs[idx / XS][idx % XS] = d_X2[(size_t)(b0 + idx / XS) * XS + (idx % XS)];
    __syncthreads();

    float acc[RPB] = {0.f, 0.f, 0.f, 0.f};
    for (int r = tid; r < TRIP2; r += 256) {
        const float w = __ldg(&d_w2t[r]);
        const int p = __ldg(&d_Tij[r]);
        const int i = p & 0xffff, j = p >> 16;
#pragma unroll
        for (int q = 0; q < RPB; q++)
            acc[q] += xs[q][i] * xs[q][j] * w;
    }
    const int lane = tid & 31, warp = tid >> 5;
#pragma unroll
    for (int q = 0; q < RPB; q++) {
        float s = acc[q];
#pragma unroll
        for (int o = 16; o > 0; o >>= 1) s += __shfl_down_sync(0xffffffffu, s, o);
        if (lane == 0) red[warp][q] = s;
    }
    __syncthreads();
    if (tid < RPB) {
        float s = 0.f;
#pragma unroll
        for (int w = 0; w < 8; w++) s += red[w][tid];
        const float pooled = s + d_b2s;
        const float z = pooled * out_w[0] + out_b[0];
        out[b0 + tid] = 1.f / (1.f + expf(-z));
    }
}

extern "C" void kernel_launch(void* const* d_in, const int* in_sizes, int n_in,
                              void* d_out, int out_size) {
    const float* dense = (const float*)d_in[0];
    const int* sparse = (const int*)d_in[1];
    const float* emb = (const float*)d_in[2];
    const float* W1 = (const float*)d_in[3];
    const float* b1 = (const float*)d_in[4];
    const float* W2 = (const float*)d_in[5];
    const float* b2 = (const float*)d_in[6];
    // d_in[7..10]: attention weights — mathematically dead (softmax over size-1 axis == 1)
    const float* out_w = (const float*)d_in[11];
    const float* out_b = (const float*)d_in[12];
    float* out = (float*)d_out;

    cudaFuncSetAttribute(gemm1_kernel, cudaFuncAttributeMaxDynamicSharedMemorySize, SMEM_GEMM);

    // Launch order chosen so gemm1 is launch #4 (the one ncu captures).
    make_pairs_kernel<<<1, 256>>>();
    pack1_kernel<<<TRIP2, 64>>>(W1);
    build_x_kernel<<<BATCH, XS>>>(dense, sparse, emb);
    gemm1_kernel<<<dim3(BATCH / BM, KSPLIT), 256, SMEM_GEMM>>>();
    w2sum_kernel<<<(TRIP2 + 7) / 8, 256>>>(W2);       // independent of gemm1
    b2sum_kernel<<<1, 256>>>(b2);
    reduce1_kernel<<<BATCH, XS>>>(b1);
    final_kernel<<<BATCH / RPB, 256>>>(out_w, out_b, out);
}

// round 8
// speedup vs baseline: 1.6087x; 1.5616x over previous
#include <cuda_runtime.h>
#include <cstdint>
#include <math.h>

// ---------------- problem constants ----------------
#define FDIM 221
#define BATCH 2048
#define XS 224
#define NPAD 256
#define DDIM 13
#define SDIM 26
#define EDIM 8
#define VDIM 100000
#define TRI 24531             // F*(F+1)/2 valid triangle rows
#define TRIP2 24544           // padded K, multiple of 32
#define BKC 32
#define CHUNKS (TRIP2 / BKC)  // 767
#define KSPLIT 9
#define CPS 86                // ceil(767/9)
#define BM 64

// ---------------- gemm smem layout (dynamic) ----------------
#define W_STG (BKC * NPAD * 4)          // 32768 B
#define A_STG (BKC * BM * 8)            // 16384 B (f32x2 duplicated pairs)
#define OFF_W0 0
#define OFF_W1 W_STG
#define OFF_A0 (2 * W_STG)
#define OFF_A1 (2 * W_STG + A_STG)
#define SMEM_GEMM (2 * W_STG + 2 * A_STG)   // 98304 B

// ---------------- scratch (device globals; no allocation APIs) ----------------
__device__ float d_X1T[FDIM * BATCH];                  // transposed x: [feature][batch]
__device__ float d_X2[BATCH * XS];
__device__ float d_Wp1[(size_t)TRIP2 * NPAD];          // 25.1 MB folded W1
__device__ float d_Yp[(size_t)KSPLIT * BATCH * NPAD];  // 18.9 MB split-K partials
__device__ float d_w2t[TRIP2];                         // folded column-sums of W2
__device__ float d_b2s;
__device__ __align__(16) int d_Tij[TRIP2];             // i | (j<<16)

// ---------------- helpers ----------------
__device__ __forceinline__ uint32_t smem_u32(const void* p) {
    uint32_t a;
    asm("{ .reg .u64 t; cvta.to.shared.u64 t, %1; cvt.u32.u64 %0, t; }" : "=r"(a) : "l"(p));
    return a;
}
__device__ __forceinline__ void cpa16(uint32_t sm, const void* g) {
    asm volatile("cp.async.cg.shared.global [%0], [%1], 16;" :: "r"(sm), "l"(g));
}
__device__ __forceinline__ void fma2(unsigned long long& acc,
                                     unsigned long long a,
                                     unsigned long long b) {
    asm("fma.rn.f32x2 %0, %1, %2, %0;" : "+l"(acc) : "l"(a), "l"(b));
}
__device__ __forceinline__ float2 unpack2f(unsigned long long v) {
    float2 f;
    asm("mov.b64 {%0, %1}, %2;" : "=f"(f.x), "=f"(f.y) : "l"(v));
    return f;
}

// ---------------- 1) packed triangle index table ----------------
__global__ void make_pairs_kernel() {
    int tid = threadIdx.x;
    for (int i = tid; i < FDIM; i += blockDim.x) {
        int start = i * FDIM - (i * (i - 1)) / 2;
        for (int j = i; j < FDIM; j++)
            d_Tij[start + j - i] = i | (j << 16);
    }
    for (int r = TRI + tid; r < TRIP2; r += blockDim.x) d_Tij[r] = 0;
}

// ---------------- 2) fold W1 -> Wp1[TRIP2][256] ----------------
__global__ void pack1_kernel(const float* __restrict__ W) {
    int r = blockIdx.x;
    float* dst = d_Wp1 + (size_t)r * NPAD;
    if (r >= TRI) {
        for (int c = threadIdx.x; c < NPAD; c += blockDim.x) dst[c] = 0.f;
        return;
    }
    int p = d_Tij[r];
    int i = p & 0xffff, j = p >> 16;
    const float* wa = W + ((size_t)i * FDIM + j) * FDIM;
    const float* wb = W + ((size_t)j * FDIM + i) * FDIM;
    for (int c = threadIdx.x; c < NPAD; c += blockDim.x) {
        float v = 0.f;
        if (c < FDIM) {
            v = wa[c];
            if (i != j) v += wb[c];
        }
        dst[c] = v;
    }
}

// ---------------- 3) fold column-sums of W2 -> w2t (layer 2 collapses to a quadratic form) ----------------
__global__ void w2sum_kernel(const float* __restrict__ W2) {
    int r = blockIdx.x * 8 + (threadIdx.x >> 5);
    int lane = threadIdx.x & 31;
    if (r >= TRIP2) return;
    float s = 0.f;
    if (r < TRI) {
        int p = d_Tij[r];
        int i = p & 0xffff, j = p >> 16;
        const float* wa = W2 + ((size_t)i * FDIM + j) * FDIM;
        const float* wb = W2 + ((size_t)j * FDIM + i) * FDIM;
        for (int f = lane; f < FDIM; f += 32) {
            s += wa[f];
            if (i != j) s += wb[f];
        }
    }
#pragma unroll
    for (int o = 16; o > 0; o >>= 1) s += __shfl_down_sync(0xffffffffu, s, o);
    if (lane == 0) d_w2t[r] = s;
}
__global__ void b2sum_kernel(const float* __restrict__ b2) {
    __shared__ float red[8];
    int lane = threadIdx.x & 31, warp = threadIdx.x >> 5;
    float s = 0.f;
    for (int f = threadIdx.x; f < FDIM; f += 256) s += b2[f];
#pragma unroll
    for (int o = 16; o > 0; o >>= 1) s += __shfl_down_sync(0xffffffffu, s, o);
    if (lane == 0) red[warp] = s;
    __syncthreads();
    if (threadIdx.x == 0) {
        float t = 0.f;
#pragma unroll
        for (int w = 0; w < 8; w++) t += red[w];
        d_b2s = t;
    }
}

// ---------------- 4) build x transposed: X1T[feature][batch] ----------------
__global__ void build_x_kernel(const float* __restrict__ dense,
                               const int* __restrict__ sparse,
                               const float* __restrict__ emb) {
    int b = blockIdx.x;
    int t = threadIdx.x;   // 224 threads; t >= FDIM writes nothing
    if (t >= FDIM) return;
    float v;
    if (t < DDIM) {
        v = dense[b * DDIM + t];
    } else {
        int q = t - DDIM;
        int s = q >> 3;
        int e = q & 7;
        int idx = sparse[b * SDIM + s];
        v = emb[((size_t)s * VDIM + idx) * EDIM + e];
    }
    d_X1T[t * BATCH + b] = v;
}

// ---------------- 5) layer-1 interaction GEMM (FFMA2, BK=32, split-K=9, 2 CTA/SM) ----------------
// Lane map: ml = lane&3 (4 m-groups), nl = lane>>2 (8 n-groups).
// Warp map: warpM = wid&1 (2 x 32 rows), warpN = wid>>1 (4 x 64 cols).
// Thread tile: 8 m (m = 8q+2ml+p, q=0..3, p=0..1) x 8 n (n = h*32+4nl+{0..3}, h=0..1).
__global__ void __launch_bounds__(256, 2) gemm1_kernel() {
    extern __shared__ __align__(16) char smem[];
    const uint32_t sb = smem_u32(smem);

    const int tid = threadIdx.x;
    const int lane = tid & 31;
    const int wid = tid >> 5;
    const int ml = lane & 3;
    const int nl = lane >> 2;
    const int warpM = wid & 1;
    const int warpN = wid >> 1;
    const int mBase = blockIdx.x * BM;
    const int split = blockIdx.y;
    const int c0 = split * CPS;
    const int c1 = min(c0 + CPS, CHUNKS);

    // producer mapping
    const int am = tid & 63;       // batch-row within tile (lanes coalesced)
    const int akg = tid >> 6;      // kk group 0..3 (8 kks each); uniform per warp
    const float* xTb = d_X1T + mBase + am;

    unsigned long long acc[8][4];  // [g=2q+p][h*2+d]
#pragma unroll
    for (int a = 0; a < 8; a++)
#pragma unroll
        for (int s = 0; s < 4; s++) acc[a][s] = 0ULL;

    auto issueW = [&](int ch, int stg) {
        const char* g = (const char*)d_Wp1 + (size_t)ch * W_STG;
        const uint32_t s0 = sb + (stg ? OFF_W1 : OFF_W0);
#pragma unroll
        for (int q = 0; q < 8; q++) {
            const int off = (tid + q * 256) * 16;
            cpa16(s0 + off, g + off);
        }
        asm volatile("cp.async.commit_group;");
    };

    int tij[8];
    float xv[16];
    auto loadNext = [&](int ch) {
        const int rb = ch * BKC + akg * 8;
        const int4* t4 = (const int4*)(d_Tij + rb);     // warp-uniform -> broadcast
        int4 p0 = __ldg(t4);
        int4 p1 = __ldg(t4 + 1);
        tij[0] = p0.x; tij[1] = p0.y; tij[2] = p0.z; tij[3] = p0.w;
        tij[4] = p1.x; tij[5] = p1.y; tij[6] = p1.z; tij[7] = p1.w;
#pragma unroll
        for (int u = 0; u < 8; u++) {                   // coalesced: lanes = consecutive batch
            xv[2 * u]     = __ldg(xTb + (size_t)(tij[u] & 0xffff) * BATCH);
            xv[2 * u + 1] = __ldg(xTb + (size_t)(tij[u] >> 16) * BATCH);
        }
    };
    auto storeA = [&](int stg) {
        float2* dst = (float2*)(smem + (stg ? OFF_A1 : OFF_A0));
#pragma unroll
        for (int u = 0; u < 8; u++) {
            const float v = xv[2 * u] * xv[2 * u + 1];
            dst[(akg * 8 + u) * BM + am] = make_float2(v, v);
        }
    };

    // prologue
    issueW(c0, 0);
    loadNext(c0);
    storeA(0);
    asm volatile("cp.async.wait_group 0;");
    __syncthreads();

    for (int ch = c0; ch < c1; ch++) {
        const int buf = (ch - c0) & 1;
        const bool hasNext = (ch + 1 < c1);
        if (hasNext) {
            issueW(ch + 1, buf ^ 1);
            loadNext(ch + 1);      // coalesced LDGs in flight under the MMA block
        }
        const float* Wb = (const float*)(smem + (buf ? OFF_W1 : OFF_W0));
        const float2* Ab = (const float2*)(smem + (buf ? OFF_A1 : OFF_A0));
#pragma unroll 8
        for (int kk = 0; kk < BKC; kk++) {
            // A: 4 x LDS.128, each = 4 consecutive 16B chunks across ml -> 1 wavefront
            unsigned long long ap[8];
#pragma unroll
            for (int q = 0; q < 4; q++) {
                ulonglong2 av = *reinterpret_cast<const ulonglong2*>(
                    Ab + kk * BM + warpM * 32 + (q * 4 + ml) * 2);
                ap[2 * q] = av.x;       // m = 8q + 2ml
                ap[2 * q + 1] = av.y;   // m = 8q + 2ml + 1
            }
            // W: 2 x LDS.128, each = 8 consecutive 16B chunks across nl -> 1 wavefront
            unsigned long long wv[4];
#pragma unroll
            for (int h = 0; h < 2; h++) {
                ulonglong2 wvv = *reinterpret_cast<const ulonglong2*>(
                    Wb + kk * NPAD + warpN * 64 + h * 32 + nl * 4);
                wv[h * 2] = wvv.x;      // cols 4nl+0,1
                wv[h * 2 + 1] = wvv.y;  // cols 4nl+2,3
            }
#pragma unroll
            for (int g = 0; g < 8; g++)
#pragma unroll
                for (int s = 0; s < 4; s++)
                    fma2(acc[g][s], ap[g], wv[s]);
        }
        if (hasNext) storeA(buf ^ 1);
        asm volatile("cp.async.wait_group 0;");
        __syncthreads();
    }

    // epilogue: deterministic split-K partial store (STG.128, lanes nl-consecutive)
#pragma unroll
    for (int g = 0; g < 8; g++) {
        const int q = g >> 1, p = g & 1;
        const int m = mBase + warpM * 32 + 8 * q + 2 * ml + p;
        float* dst = d_Yp + ((size_t)split * BATCH + m) * NPAD + warpN * 64 + nl * 4;
#pragma unroll
        for (int h = 0; h < 2; h++) {
            float2 lo = unpack2f(acc[g][h * 2]);
            float2 hi = unpack2f(acc[g][h * 2 + 1]);
            *reinterpret_cast<float4*>(dst + h * 32) = make_float4(lo.x, lo.y, hi.x, hi.y);
        }
    }
}

// ---------------- 6) reduce split-K partials + bias -> X2 (zero-padded to 224) ----------------
__global__ void reduce1_kernel(const float* __restrict__ b1) {
    int m = blockIdx.x;
    int c = threadIdx.x;
    float v = 0.f;
    if (c < FDIM) {
        v = b1[c];
#pragma unroll
        for (int p = 0; p < KSPLIT; p++)
            v += d_Yp[((size_t)p * BATCH + m) * NPAD + c];
    }
    d_X2[m * XS + c] = v;
}

// ---------------- 7) final: pooled = x2^T S2 x2 + sum(b2); sigmoid ----------------
#define RPB 4
__global__ void final_kernel(const float* __restrict__ out_w,
                             const float* __restrict__ out_b,
                             float* __restrict__ out) {
    __shared__ float xs[RPB][XS];
    __shared__ float red[8][RPB];
    const int tid = threadIdx.x;
    const int b0 = blockIdx.x * RPB;
    for (int idx = tid; idx < RPB * XS; idx += 256)
        xs[idx / XS][idx % XS] = d_X2[(size_t)(b0 + idx / XS) * XS + (idx % XS)];
    __syncthreads();

    float acc[RPB] = {0.f, 0.f, 0.f, 0.f};
    for (int r = tid; r < TRIP2; r += 256) {
        const float w = __ldg(&d_w2t[r]);
        const int p = __ldg(&d_Tij[r]);
        const int i = p & 0xffff, j = p >> 16;
#pragma unroll
        for (int q = 0; q < RPB; q++)
            acc[q] += xs[q][i] * xs[q][j] * w;
    }
    const int lane = tid & 31, warp = tid >> 5;
#pragma unroll
    for (int q = 0; q < RPB; q++) {
        float s = acc[q];
#pragma unroll
        for (int o = 16; o > 0; o >>= 1) s += __shfl_down_sync(0xffffffffu, s, o);
        if (lane == 0) red[warp][q] = s;
    }
    __syncthreads();
    if (tid < RPB) {
        float s = 0.f;
#pragma unroll
        for (int w = 0; w < 8; w++) s += red[w][tid];
        const float pooled = s + d_b2s;
        const float z = pooled * out_w[0] + out_b[0];
        out[b0 + tid] = 1.f / (1.f + expf(-z));
    }
}

extern "C" void kernel_launch(void* const* d_in, const int* in_sizes, int n_in,
                              void* d_out, int out_size) {
    const float* dense = (const float*)d_in[0];
    const int* sparse = (const int*)d_in[1];
    const float* emb = (const float*)d_in[2];
    const float* W1 = (const float*)d_in[3];
    const float* b1 = (const float*)d_in[4];
    const float* W2 = (const float*)d_in[5];
    const float* b2 = (const float*)d_in[6];
    // d_in[7..10]: attention weights — mathematically dead (softmax over size-1 axis == 1)
    const float* out_w = (const float*)d_in[11];
    const float* out_b = (const float*)d_in[12];
    float* out = (float*)d_out;

    cudaFuncSetAttribute(gemm1_kernel, cudaFuncAttributeMaxDynamicSharedMemorySize, SMEM_GEMM);

    // Launch order keeps gemm1 as launch #4 (the one ncu captures).
    make_pairs_kernel<<<1, 256>>>();
    pack1_kernel<<<TRIP2, 64>>>(W1);
    build_x_kernel<<<BATCH, XS>>>(dense, sparse, emb);
    gemm1_kernel<<<dim3(BATCH / BM, KSPLIT), 256, SMEM_GEMM>>>();
    w2sum_kernel<<<(TRIP2 + 7) / 8, 256>>>(W2);       // independent of gemm1
    b2sum_kernel<<<1, 256>>>(b2);
    reduce1_kernel<<<BATCH, XS>>>(b1);
    final_kernel<<<BATCH / RPB, 256>>>(out_w, out_b, out);
}

// round 11
// speedup vs baseline: 1.6382x; 1.0183x over previous
#include <cuda_runtime.h>
#include <cstdint>
#include <math.h>

// ---------------- problem constants ----------------
#define FDIM 221
#define BATCH 2048
#define XS 224
#define NPAD 256
#define DDIM 13
#define SDIM 26
#define EDIM 8
#define VDIM 100000
#define TRI 24531             // F*(F+1)/2 valid triangle rows
#define TRIP2 24544           // padded K, multiple of 32
#define BKC 32
#define CHUNKS (TRIP2 / BKC)  // 767
#define KSPLIT 9
#define CPS 86                // ceil(767/9)
#define BM 64

// ---------------- gemm smem layout (dynamic) ----------------
#define W_STG (BKC * NPAD * 4)          // 32768 B
#define A_STG (BKC * BM * 8)            // 16384 B (f32x2 duplicated pairs)
#define OFF_W0 0
#define OFF_W1 W_STG
#define OFF_A0 (2 * W_STG)
#define OFF_A1 (2 * W_STG + A_STG)
#define SMEM_GEMM (2 * W_STG + 2 * A_STG)   // 98304 B

// ---------------- scratch (device globals; no allocation APIs) ----------------
__device__ float d_X1T[FDIM * BATCH];                  // transposed x: [feature][batch]
__device__ float d_X2[BATCH * XS];
__device__ float d_Wp1[(size_t)TRIP2 * NPAD];          // 25.1 MB folded W1
__device__ float d_Yp[(size_t)KSPLIT * BATCH * NPAD];  // 18.9 MB split-K partials
__device__ float d_w2t[TRIP2];                         // folded column-sums of W2
__device__ float d_b2s;
__device__ __align__(16) int d_Tij[TRIP2];             // i | (j<<16)

// ---------------- helpers ----------------
__device__ __forceinline__ uint32_t smem_u32(const void* p) {
    uint32_t a;
    asm("{ .reg .u64 t; cvta.to.shared.u64 t, %1; cvt.u32.u64 %0, t; }" : "=r"(a) : "l"(p));
    return a;
}
__device__ __forceinline__ void cpa16(uint32_t sm, const void* g) {
    asm volatile("cp.async.cg.shared.global [%0], [%1], 16;" :: "r"(sm), "l"(g));
}
__device__ __forceinline__ void fma2(unsigned long long& acc,
                                     unsigned long long a,
                                     unsigned long long b) {
    asm("fma.rn.f32x2 %0, %1, %2, %0;" : "+l"(acc) : "l"(a), "l"(b));
}
__device__ __forceinline__ float2 unpack2f(unsigned long long v) {
    float2 f;
    asm("mov.b64 {%0, %1}, %2;" : "=f"(f.x), "=f"(f.y) : "l"(v));
    return f;
}

// ---------------- 1) packed triangle index table ----------------
__global__ void make_pairs_kernel() {
    int tid = threadIdx.x;
    for (int i = tid; i < FDIM; i += blockDim.x) {
        int start = i * FDIM - (i * (i - 1)) / 2;
        for (int j = i; j < FDIM; j++)
            d_Tij[start + j - i] = i | (j << 16);
    }
    for (int r = TRI + tid; r < TRIP2; r += blockDim.x) d_Tij[r] = 0;
}

// ---------------- 2) fold W1 -> Wp1[TRIP2][256] ----------------
__global__ void pack1_kernel(const float* __restrict__ W) {
    int r = blockIdx.x;
    float* dst = d_Wp1 + (size_t)r * NPAD;
    if (r >= TRI) {
        for (int c = threadIdx.x; c < NPAD; c += blockDim.x) dst[c] = 0.f;
        return;
    }
    int p = d_Tij[r];
    int i = p & 0xffff, j = p >> 16;
    const float* wa = W + ((size_t)i * FDIM + j) * FDIM;
    const float* wb = W + ((size_t)j * FDIM + i) * FDIM;
    for (int c = threadIdx.x; c < NPAD; c += blockDim.x) {
        float v = 0.f;
        if (c < FDIM) {
            v = wa[c];
            if (i != j) v += wb[c];
        }
        dst[c] = v;
    }
}

// ---------------- 3) fold column-sums of W2 -> w2t (layer 2 collapses to a quadratic form) ----------------
__global__ void w2sum_kernel(const float* __restrict__ W2) {
    int r = blockIdx.x * 8 + (threadIdx.x >> 5);
    int lane = threadIdx.x & 31;
    if (r >= TRIP2) return;
    float s = 0.f;
    if (r < TRI) {
        int p = d_Tij[r];
        int i = p & 0xffff, j = p >> 16;
        const float* wa = W2 + ((size_t)i * FDIM + j) * FDIM;
        const float* wb = W2 + ((size_t)j * FDIM + i) * FDIM;
        for (int f = lane; f < FDIM; f += 32) {
            s += wa[f];
            if (i != j) s += wb[f];
        }
    }
#pragma unroll
    for (int o = 16; o > 0; o >>= 1) s += __shfl_down_sync(0xffffffffu, s, o);
    if (lane == 0) d_w2t[r] = s;
}
__global__ void b2sum_kernel(const float* __restrict__ b2) {
    __shared__ float red[8];
    int lane = threadIdx.x & 31, warp = threadIdx.x >> 5;
    float s = 0.f;
    for (int f = threadIdx.x; f < FDIM; f += 256) s += b2[f];
#pragma unroll
    for (int o = 16; o > 0; o >>= 1) s += __shfl_down_sync(0xffffffffu, s, o);
    if (lane == 0) red[warp] = s;
    __syncthreads();
    if (threadIdx.x == 0) {
        float t = 0.f;
#pragma unroll
        for (int w = 0; w < 8; w++) t += red[w];
        d_b2s = t;
    }
}

// ---------------- 4) build x transposed: X1T[feature][batch] ----------------
__global__ void build_x_kernel(const float* __restrict__ dense,
                               const int* __restrict__ sparse,
                               const float* __restrict__ emb) {
    int b = blockIdx.x;
    int t = threadIdx.x;
    if (t >= FDIM) return;
    float v;
    if (t < DDIM) {
        v = dense[b * DDIM + t];
    } else {
        int q = t - DDIM;
        int s = q >> 3;
        int e = q & 7;
        int idx = sparse[b * SDIM + s];
        v = emb[((size_t)s * VDIM + idx) * EDIM + e];
    }
    d_X1T[t * BATCH + b] = v;
}

// ---------------- 5) layer-1 interaction GEMM (FFMA2, BK=32, split-K=9, 2 CTA/SM) ----------------
// Lane map: ml = lane&3 (4 m-groups), nl = lane>>2 (8 n-groups).
// Warp map: warpM = wid&1 (2 x 32 rows), warpN = wid>>1 (4 x 64 cols).
// Register-level software pipeline: per-q A loads interleaved with FMAs; W prefetched one kk ahead.
__global__ void __launch_bounds__(256, 2) gemm1_kernel() {
    extern __shared__ __align__(16) char smem[];
    const uint32_t sb = smem_u32(smem);

    const int tid = threadIdx.x;
    const int lane = tid & 31;
    const int wid = tid >> 5;
    const int ml = lane & 3;
    const int nl = lane >> 2;
    const int warpM = wid & 1;
    const int warpN = wid >> 1;
    const int mBase = blockIdx.x * BM;
    const int split = blockIdx.y;
    const int c0 = split * CPS;
    const int c1 = min(c0 + CPS, CHUNKS);

    // producer mapping
    const int am = tid & 63;       // batch-row within tile (lanes coalesced)
    const int akg = tid >> 6;      // kk group 0..3 (8 kks each); uniform per warp
    const float* xTb = d_X1T + mBase + am;

    unsigned long long acc[8][4];  // [g=2q+p][h*2+d]
#pragma unroll
    for (int a = 0; a < 8; a++)
#pragma unroll
        for (int s = 0; s < 4; s++) acc[a][s] = 0ULL;

    auto issueW = [&](int ch, int stg) {
        const char* g = (const char*)d_Wp1 + (size_t)ch * W_STG;
        const uint32_t s0 = sb + (stg ? OFF_W1 : OFF_W0);
#pragma unroll
        for (int q = 0; q < 8; q++) {
            const int off = (tid + q * 256) * 16;
            cpa16(s0 + off, g + off);
        }
        asm volatile("cp.async.commit_group;");
    };

    float pv[8];   // this thread's 8 A-products for the next chunk
    auto loadNext = [&](int ch) {
        const int rb = ch * BKC + akg * 8;
        const int4* t4 = (const int4*)(d_Tij + rb);     // warp-uniform -> broadcast
        int4 p0 = __ldg(t4);
        int4 p1 = __ldg(t4 + 1);
        int tj[8] = {p0.x, p0.y, p0.z, p0.w, p1.x, p1.y, p1.z, p1.w};
#pragma unroll
        for (int u = 0; u < 8; u++) {                   // coalesced: lanes = consecutive batch
            float a = __ldg(xTb + (size_t)(tj[u] & 0xffff) * BATCH);
            float b = __ldg(xTb + (size_t)(tj[u] >> 16) * BATCH);
            pv[u] = a * b;
        }
    };
    auto storeA = [&](int stg) {
        float2* dst = (float2*)(smem + (stg ? OFF_A1 : OFF_A0));
#pragma unroll
        for (int u = 0; u < 8; u++)
            dst[(akg * 8 + u) * BM + am] = make_float2(pv[u], pv[u]);
    };

    // consumer per-lane byte offsets within a stage
    const int wLaneOff = (warpN * 64 + nl * 4) * 4;      // bytes into each W row
    const int aLaneOff = warpM * 256 + ml * 16;          // bytes: float2 index warpM*32 + ml*2

    // prologue
    issueW(c0, 0);
    loadNext(c0);
    storeA(0);
    asm volatile("cp.async.wait_group 0;");
    __syncthreads();

    for (int ch = c0; ch < c1; ch++) {
        const int buf = (ch - c0) & 1;
        const bool hasNext = (ch + 1 < c1);
        if (hasNext) {
            issueW(ch + 1, buf ^ 1);
            loadNext(ch + 1);      // coalesced LDGs in flight under the MMA block
        }
        const char* Wb = smem + (buf ? OFF_W1 : OFF_W0) + wLaneOff;
        const char* Ab = smem + (buf ? OFF_A1 : OFF_A0) + aLaneOff;

        // ---- software-pipelined kk loop ----
        ulonglong2 av_cur, av_nxt;
        unsigned long long wv_cur[4], wv_nxt[4];
        {   // preload kk=0, q=0
            ulonglong2 w0 = *reinterpret_cast<const ulonglong2*>(Wb);
            ulonglong2 w1 = *reinterpret_cast<const ulonglong2*>(Wb + 128);
            wv_cur[0] = w0.x; wv_cur[1] = w0.y; wv_cur[2] = w1.x; wv_cur[3] = w1.y;
            av_cur = *reinterpret_cast<const ulonglong2*>(Ab);
        }
#pragma unroll
        for (int kk = 0; kk < BKC; kk++) {
            const char* Arow = Ab + kk * (BM * 8);
            const char* Wrow = Wb + kk * (NPAD * 4);
            if (kk + 1 < BKC) {
                const char* Wn = Wrow + NPAD * 4;
                ulonglong2 w0 = *reinterpret_cast<const ulonglong2*>(Wn);
                ulonglong2 w1 = *reinterpret_cast<const ulonglong2*>(Wn + 128);
                wv_nxt[0] = w0.x; wv_nxt[1] = w0.y; wv_nxt[2] = w1.x; wv_nxt[3] = w1.y;
            }
#pragma unroll
            for (int q = 0; q < 4; q++) {
                if (q < 3)
                    av_nxt = *reinterpret_cast<const ulonglong2*>(Arow + (q + 1) * 64);
                else if (kk + 1 < BKC)
                    av_nxt = *reinterpret_cast<const ulonglong2*>(Arow + BM * 8);
#pragma unroll
                for (int s = 0; s < 4; s++) {
                    fma2(acc[2 * q][s], av_cur.x, wv_cur[s]);
                    fma2(acc[2 * q + 1][s], av_cur.y, wv_cur[s]);
                }
                av_cur = av_nxt;
            }
            wv_cur[0] = wv_nxt[0]; wv_cur[1] = wv_nxt[1];
            wv_cur[2] = wv_nxt[2]; wv_cur[3] = wv_nxt[3];
        }

        if (hasNext) storeA(buf ^ 1);
        asm volatile("cp.async.wait_group 0;");
        __syncthreads();
    }

    // epilogue: deterministic split-K partial store (STG.128, lanes nl-consecutive)
#pragma unroll
    for (int g = 0; g < 8; g++) {
        const int q = g >> 1, p = g & 1;
        const int m = mBase + warpM * 32 + 8 * q + 2 * ml + p;
        float* dst = d_Yp + ((size_t)split * BATCH + m) * NPAD + warpN * 64 + nl * 4;
#pragma unroll
        for (int h = 0; h < 2; h++) {
            float2 lo = unpack2f(acc[g][h * 2]);
            float2 hi = unpack2f(acc[g][h * 2 + 1]);
            *reinterpret_cast<float4*>(dst + h * 32) = make_float4(lo.x, lo.y, hi.x, hi.y);
        }
    }
}

// ---------------- 6) reduce split-K partials + bias -> X2 (zero-padded to 224) ----------------
__global__ void reduce1_kernel(const float* __restrict__ b1) {
    int m = blockIdx.x;
    int c = threadIdx.x;
    float v = 0.f;
    if (c < FDIM) {
        v = b1[c];
#pragma unroll
        for (int p = 0; p < KSPLIT; p++)
            v += d_Yp[((size_t)p * BATCH + m) * NPAD + c];
    }
    d_X2[m * XS + c] = v;
}

// ---------------- 7) final: pooled = x2^T S2 x2 + sum(b2); sigmoid ----------------
#define RPB 4
__global__ void final_kernel(const float* __restrict__ out_w,
                             const float* __restrict__ out_b,
                             float* __restrict__ out) {
    __shared__ float xs[RPB][XS];
    __shared__ float red[8][RPB];
    const int tid = threadIdx.x;
    const int b0 = blockIdx.x * RPB;
    for (int idx = tid; idx < RPB * XS; idx += 256)
        xs[idx / XS][idx % XS] = d_X2[(size_t)(b0 + idx / XS) * XS + (idx % XS)];
    __syncthreads();

    float acc[RPB] = {0.f, 0.f, 0.f, 0.f};
    for (int r = tid; r < TRIP2; r += 256) {
        const float w = __ldg(&d_w2t[r]);
        const int p = __ldg(&d_Tij[r]);
        const int i = p & 0xffff, j = p >> 16;
#pragma unroll
        for (int q = 0; q < RPB; q++)
            acc[q] += xs[q][i] * xs[q][j] * w;
    }
    const int lane = tid & 31, warp = tid >> 5;
#pragma unroll
    for (int q = 0; q < RPB; q++) {
        float s = acc[q];
#pragma unroll
        for (int o = 16; o > 0; o >>= 1) s += __shfl_down_sync(0xffffffffu, s, o);
        if (lane == 0) red[warp][q] = s;
    }
    __syncthreads();
    if (tid < RPB) {
        float s = 0.f;
#pragma unroll
        for (int w = 0; w < 8; w++) s += red[w][tid];
        const float pooled = s + d_b2s;
        const float z = pooled * out_w[0] + out_b[0];
        out[b0 + tid] = 1.f / (1.f + expf(-z));
    }
}

extern "C" void kernel_launch(void* const* d_in, const int* in_sizes, int n_in,
                              void* d_out, int out_size) {
    const float* dense = (const float*)d_in[0];
    const int* sparse = (const int*)d_in[1];
    const float* emb = (const float*)d_in[2];
    const float* W1 = (const float*)d_in[3];
    const float* b1 = (const float*)d_in[4];
    const float* W2 = (const float*)d_in[5];
    const float* b2 = (const float*)d_in[6];
    // d_in[7..10]: attention weights — mathematically dead (softmax over size-1 axis == 1)
    const float* out_w = (const float*)d_in[11];
    const float* out_b = (const float*)d_in[12];
    float* out = (float*)d_out;

    cudaFuncSetAttribute(gemm1_kernel, cudaFuncAttributeMaxDynamicSharedMemorySize, SMEM_GEMM);

    // Launch order keeps gemm1 as launch #4 (the one ncu captures).
    make_pairs_kernel<<<1, 256>>>();
    pack1_kernel<<<TRIP2, 64>>>(W1);
    build_x_kernel<<<BATCH, XS>>>(dense, sparse, emb);
    gemm1_kernel<<<dim3(BATCH / BM, KSPLIT), 256, SMEM_GEMM>>>();
    w2sum_kernel<<<(TRIP2 + 7) / 8, 256>>>(W2);       // independent of gemm1
    b2sum_kernel<<<1, 256>>>(b2);
    reduce1_kernel<<<BATCH, XS>>>(b1);
    final_kernel<<<BATCH / RPB, 256>>>(out_w, out_b, out);
}

// round 12
// speedup vs baseline: 1.8164x; 1.1088x over previous
#include <cuda_runtime.h>
#include <cstdint>
#include <math.h>

// ---------------- problem constants ----------------
#define FDIM 221
#define BATCH 2048
#define XS 224
#define NPAD 256
#define DDIM 13
#define SDIM 26
#define EDIM 8
#define VDIM 100000
#define TRI 24531             // F*(F+1)/2 valid triangle rows
#define TRIP2 24544           // padded K, multiple of 32
#define BKC 32
#define CHUNKS (TRIP2 / BKC)  // 767
#define KSPLIT 9
#define CPS 86                // ceil(767/9)
#define BM 64

// ---------------- gemm smem layout (dynamic) ----------------
#define W_STG (BKC * NPAD * 4)          // 32768 B
#define A_STG (BKC * BM * 4)            // 8192 B (plain f32, unduplicated)
#define OFF_W0 0
#define OFF_W1 W_STG
#define OFF_A0 (2 * W_STG)
#define OFF_A1 (2 * W_STG + A_STG)
#define SMEM_GEMM (2 * W_STG + 2 * A_STG)   // 81920 B

// ---------------- scratch (device globals; no allocation APIs) ----------------
__device__ float d_X1T[FDIM * BATCH];                  // transposed x: [feature][batch]
__device__ float d_X2[BATCH * XS];
__device__ float d_Wp1[(size_t)TRIP2 * NPAD];          // 25.1 MB folded W1
__device__ float d_Yp[(size_t)KSPLIT * BATCH * NPAD];  // 18.9 MB split-K partials
__device__ float d_w2t[TRIP2];                         // folded column-sums of W2
__device__ float d_b2s;
__device__ __align__(16) int d_Tij[TRIP2];             // i | (j<<16)

// ---------------- helpers ----------------
__device__ __forceinline__ uint32_t smem_u32(const void* p) {
    uint32_t a;
    asm("{ .reg .u64 t; cvta.to.shared.u64 t, %1; cvt.u32.u64 %0, t; }" : "=r"(a) : "l"(p));
    return a;
}
__device__ __forceinline__ void cpa16(uint32_t sm, const void* g) {
    asm volatile("cp.async.cg.shared.global [%0], [%1], 16;" :: "r"(sm), "l"(g));
}
__device__ __forceinline__ void fma2(unsigned long long& acc,
                                     unsigned long long a,
                                     unsigned long long b) {
    asm("fma.rn.f32x2 %0, %1, %2, %0;" : "+l"(acc) : "l"(a), "l"(b));
}
__device__ __forceinline__ unsigned long long pack2f(float x) {
    unsigned long long r;
    asm("mov.b64 %0, {%1, %1};" : "=l"(r) : "f"(x));
    return r;
}
__device__ __forceinline__ float2 unpack2f(unsigned long long v) {
    float2 f;
    asm("mov.b64 {%0, %1}, %2;" : "=f"(f.x), "=f"(f.y) : "l"(v));
    return f;
}

// ---------------- 1) packed triangle index table ----------------
__global__ void make_pairs_kernel() {
    int tid = threadIdx.x;
    for (int i = tid; i < FDIM; i += blockDim.x) {
        int start = i * FDIM - (i * (i - 1)) / 2;
        for (int j = i; j < FDIM; j++)
            d_Tij[start + j - i] = i | (j << 16);
    }
    for (int r = TRI + tid; r < TRIP2; r += blockDim.x) d_Tij[r] = 0;
}

// ---------------- 2) fold W1 -> Wp1[TRIP2][256] ----------------
__global__ void pack1_kernel(const float* __restrict__ W) {
    int r = blockIdx.x;
    float* dst = d_Wp1 + (size_t)r * NPAD;
    if (r >= TRI) {
        for (int c = threadIdx.x; c < NPAD; c += blockDim.x) dst[c] = 0.f;
        return;
    }
    int p = d_Tij[r];
    int i = p & 0xffff, j = p >> 16;
    const float* wa = W + ((size_t)i * FDIM + j) * FDIM;
    const float* wb = W + ((size_t)j * FDIM + i) * FDIM;
    for (int c = threadIdx.x; c < NPAD; c += blockDim.x) {
        float v = 0.f;
        if (c < FDIM) {
            v = wa[c];
            if (i != j) v += wb[c];
        }
        dst[c] = v;
    }
}

// ---------------- 3) fold column-sums of W2 -> w2t (layer 2 collapses to a quadratic form) ----------------
__global__ void w2sum_kernel(const float* __restrict__ W2) {
    int r = blockIdx.x * 8 + (threadIdx.x >> 5);
    int lane = threadIdx.x & 31;
    if (r >= TRIP2) return;
    float s = 0.f;
    if (r < TRI) {
        int p = d_Tij[r];
        int i = p & 0xffff, j = p >> 16;
        const float* wa = W2 + ((size_t)i * FDIM + j) * FDIM;
        const float* wb = W2 + ((size_t)j * FDIM + i) * FDIM;
        for (int f = lane; f < FDIM; f += 32) {
            s += wa[f];
            if (i != j) s += wb[f];
        }
    }
#pragma unroll
    for (int o = 16; o > 0; o >>= 1) s += __shfl_down_sync(0xffffffffu, s, o);
    if (lane == 0) d_w2t[r] = s;
}
__global__ void b2sum_kernel(const float* __restrict__ b2) {
    __shared__ float red[8];
    int lane = threadIdx.x & 31, warp = threadIdx.x >> 5;
    float s = 0.f;
    for (int f = threadIdx.x; f < FDIM; f += 256) s += b2[f];
#pragma unroll
    for (int o = 16; o > 0; o >>= 1) s += __shfl_down_sync(0xffffffffu, s, o);
    if (lane == 0) red[warp] = s;
    __syncthreads();
    if (threadIdx.x == 0) {
        float t = 0.f;
#pragma unroll
        for (int w = 0; w < 8; w++) t += red[w];
        d_b2s = t;
    }
}

// ---------------- 4) build x transposed: X1T[feature][batch] ----------------
__global__ void build_x_kernel(const float* __restrict__ dense,
                               const int* __restrict__ sparse,
                               const float* __restrict__ emb) {
    int b = blockIdx.x;
    int t = threadIdx.x;
    if (t >= FDIM) return;
    float v;
    if (t < DDIM) {
        v = dense[b * DDIM + t];
    } else {
        int q = t - DDIM;
        int s = q >> 3;
        int e = q & 7;
        int idx = sparse[b * SDIM + s];
        v = emb[((size_t)s * VDIM + idx) * EDIM + e];
    }
    d_X1T[t * BATCH + b] = v;
}

// ---------------- 5) layer-1 interaction GEMM (FFMA2, BK=32, split-K=9, 2 CTA/SM) ----------------
// Lane map: ml = lane&3 (4 m-groups of 8 consecutive m), nl = lane>>2 (8 n-groups).
// Warp map: warpM = wid&1 (2 x 32 rows), warpN = wid>>1 (4 x 64 cols).
// A stored unduplicated f32 in smem; per-kk register duplication via mov.b64 {x,x}.
__global__ void __launch_bounds__(256, 2) gemm1_kernel() {
    extern __shared__ __align__(16) char smem[];
    const uint32_t sb = smem_u32(smem);

    const int tid = threadIdx.x;
    const int lane = tid & 31;
    const int wid = tid >> 5;
    const int ml = lane & 3;
    const int nl = lane >> 2;
    const int warpM = wid & 1;
    const int warpN = wid >> 1;
    const int mBase = blockIdx.x * BM;
    const int split = blockIdx.y;
    const int c0 = split * CPS;
    const int c1 = min(c0 + CPS, CHUNKS);

    // producer mapping
    const int am = tid & 63;       // batch-row within tile (lanes coalesced)
    const int akg = tid >> 6;      // kk group 0..3 (8 kks each); uniform per warp
    const float* xTb = d_X1T + mBase + am;

    unsigned long long acc[8][4];  // [g: m = ml*8+g][pair s: cols warpN*64 + (s>>1)*32 + nl*4 + 2*(s&1)]
#pragma unroll
    for (int a = 0; a < 8; a++)
#pragma unroll
        for (int s = 0; s < 4; s++) acc[a][s] = 0ULL;

    auto issueW = [&](int ch, int stg) {
        const char* g = (const char*)d_Wp1 + (size_t)ch * W_STG;
        const uint32_t s0 = sb + (stg ? OFF_W1 : OFF_W0);
#pragma unroll
        for (int q = 0; q < 8; q++) {
            const int off = (tid + q * 256) * 16;
            cpa16(s0 + off, g + off);
        }
        asm volatile("cp.async.commit_group;");
    };

    float pv[8];   // this thread's 8 A-products for the next chunk
    auto loadNext = [&](int ch) {
        const int rb = ch * BKC + akg * 8;
        const int4* t4 = (const int4*)(d_Tij + rb);     // warp-uniform -> broadcast
        int4 p0 = __ldg(t4);
        int4 p1 = __ldg(t4 + 1);
        int tj[8] = {p0.x, p0.y, p0.z, p0.w, p1.x, p1.y, p1.z, p1.w};
#pragma unroll
        for (int u = 0; u < 8; u++) {                   // coalesced: lanes = consecutive batch
            float a = __ldg(xTb + (size_t)(tj[u] & 0xffff) * BATCH);
            float b = __ldg(xTb + (size_t)(tj[u] >> 16) * BATCH);
            pv[u] = a * b;
        }
    };
    auto storeA = [&](int stg) {
        float* dst = (float*)(smem + (stg ? OFF_A1 : OFF_A0));
#pragma unroll
        for (int u = 0; u < 8; u++)
            dst[(akg * 8 + u) * BM + am] = pv[u];       // 128B contiguous per warp
    };

    // consumer per-lane byte offsets within a stage
    const int wLaneOff = (warpN * 64 + nl * 4) * 4;      // bytes into each W row
    const int aLaneOff = (warpM * 32 + ml * 8) * 4;      // bytes into each A row (plain f32)

    // prologue
    issueW(c0, 0);
    loadNext(c0);
    storeA(0);
    asm volatile("cp.async.wait_group 0;");
    __syncthreads();

    for (int ch = c0; ch < c1; ch++) {
        const int buf = (ch - c0) & 1;
        const bool hasNext = (ch + 1 < c1);
        if (hasNext) {
            issueW(ch + 1, buf ^ 1);
            loadNext(ch + 1);      // coalesced LDGs in flight under the MMA block
        }
        const char* Wb = smem + (buf ? OFF_W1 : OFF_W0) + wLaneOff;
        const char* Ab = smem + (buf ? OFF_A1 : OFF_A0) + aLaneOff;

#pragma unroll 8
        for (int kk = 0; kk < BKC; kk++) {
            const char* Arow = Ab + kk * (BM * 4);
            const char* Wrow = Wb + kk * (NPAD * 4);
            // A: 8 distinct m-values, 2 x LDS.128 (32B returned per lane)
            float4 a0 = *reinterpret_cast<const float4*>(Arow);
            float4 a1 = *reinterpret_cast<const float4*>(Arow + 16);
            // W: 8 n-values as natural f32 pairs, 2 x LDS.128 (32B returned per lane)
            ulonglong2 w0 = *reinterpret_cast<const ulonglong2*>(Wrow);
            ulonglong2 w1 = *reinterpret_cast<const ulonglong2*>(Wrow + 128);
            unsigned long long wv[4] = {w0.x, w0.y, w1.x, w1.y};
            // register duplication of A (alu pipe)
            unsigned long long ad[8];
            ad[0] = pack2f(a0.x); ad[1] = pack2f(a0.y);
            ad[2] = pack2f(a0.z); ad[3] = pack2f(a0.w);
            ad[4] = pack2f(a1.x); ad[5] = pack2f(a1.y);
            ad[6] = pack2f(a1.z); ad[7] = pack2f(a1.w);
#pragma unroll
            for (int g = 0; g < 8; g++)
#pragma unroll
                for (int s = 0; s < 4; s++)
                    fma2(acc[g][s], ad[g], wv[s]);
        }

        if (hasNext) storeA(buf ^ 1);
        asm volatile("cp.async.wait_group 0;");
        __syncthreads();
    }

    // epilogue: deterministic split-K partial store (STG.128, lanes nl-consecutive)
#pragma unroll
    for (int g = 0; g < 8; g++) {
        const int m = mBase + warpM * 32 + ml * 8 + g;
        float* dst = d_Yp + ((size_t)split * BATCH + m) * NPAD + warpN * 64 + nl * 4;
#pragma unroll
        for (int h = 0; h < 2; h++) {
            float2 lo = unpack2f(acc[g][h * 2]);
            float2 hi = unpack2f(acc[g][h * 2 + 1]);
            *reinterpret_cast<float4*>(dst + h * 32) = make_float4(lo.x, lo.y, hi.x, hi.y);
        }
    }
}

// ---------------- 6) reduce split-K partials + bias -> X2 (zero-padded to 224) ----------------
__global__ void reduce1_kernel(const float* __restrict__ b1) {
    int m = blockIdx.x;
    int c = threadIdx.x;
    float v = 0.f;
    if (c < FDIM) {
        v = b1[c];
#pragma unroll
        for (int p = 0; p < KSPLIT; p++)
            v += d_Yp[((size_t)p * BATCH + m) * NPAD + c];
    }
    d_X2[m * XS + c] = v;
}

// ---------------- 7) final: pooled = x2^T S2 x2 + sum(b2); sigmoid ----------------
#define RPB 4
__global__ void final_kernel(const float* __restrict__ out_w,
                             const float* __restrict__ out_b,
                             float* __restrict__ out) {
    __shared__ float xs[RPB][XS];
    __shared__ float red[8][RPB];
    const int tid = threadIdx.x;
    const int b0 = blockIdx.x * RPB;
    for (int idx = tid; idx < RPB * XS; idx += 256)
        xs[idx / XS][idx % XS] = d_X2[(size_t)(b0 + idx / XS) * XS + (idx % XS)];
    __syncthreads();

    float acc[RPB] = {0.f, 0.f, 0.f, 0.f};
    for (int r = tid; r < TRIP2; r += 256) {
        const float w = __ldg(&d_w2t[r]);
        const int p = __ldg(&d_Tij[r]);
        const int i = p & 0xffff, j = p >> 16;
#pragma unroll
        for (int q = 0; q < RPB; q++)
            acc[q] += xs[q][i] * xs[q][j] * w;
    }
    const int lane = tid & 31, warp = tid >> 5;
#pragma unroll
    for (int q = 0; q < RPB; q++) {
        float s = acc[q];
#pragma unroll
        for (int o = 16; o > 0; o >>= 1) s += __shfl_down_sync(0xffffffffu, s, o);
        if (lane == 0) red[warp][q] = s;
    }
    __syncthreads();
    if (tid < RPB) {
        float s = 0.f;
#pragma unroll
        for (int w = 0; w < 8; w++) s += red[w][tid];
        const float pooled = s + d_b2s;
        const float z = pooled * out_w[0] + out_b[0];
        out[b0 + tid] = 1.f / (1.f + expf(-z));
    }
}

extern "C" void kernel_launch(void* const* d_in, const int* in_sizes, int n_in,
                              void* d_out, int out_size) {
    const float* dense = (const float*)d_in[0];
    const int* sparse = (const int*)d_in[1];
    const float* emb = (const float*)d_in[2];
    const float* W1 = (const float*)d_in[3];
    const float* b1 = (const float*)d_in[4];
    const float* W2 = (const float*)d_in[5];
    const float* b2 = (const float*)d_in[6];
    // d_in[7..10]: attention weights — mathematically dead (softmax over size-1 axis == 1)
    const float* out_w = (const float*)d_in[11];
    const float* out_b = (const float*)d_in[12];
    float* out = (float*)d_out;

    cudaFuncSetAttribute(gemm1_kernel, cudaFuncAttributeMaxDynamicSharedMemorySize, SMEM_GEMM);

    // Launch order keeps gemm1 as launch #4 (the one ncu captures).
    make_pairs_kernel<<<1, 256>>>();
    pack1_kernel<<<TRIP2, 64>>>(W1);
    build_x_kernel<<<BATCH, XS>>>(dense, sparse, emb);
    gemm1_kernel<<<dim3(BATCH / BM, KSPLIT), 256, SMEM_GEMM>>>();
    w2sum_kernel<<<(TRIP2 + 7) / 8, 256>>>(W2);       // independent of gemm1
    b2sum_kernel<<<1, 256>>>(b2);
    reduce1_kernel<<<BATCH, XS>>>(b1);
    final_kernel<<<BATCH / RPB, 256>>>(out_w, out_b, out);
}